// round 10
// baseline (speedup 1.0000x reference)
#include <cuda_runtime.h>
#include <cuda_bf16.h>
#include <cstdint>
#include <float.h>

#define Nn    16384
#define Dd    128
#define KK    32
#define BM    128        // rows per CTA
#define BN    64         // cols per j-tile
#define NT    (Nn / BN)  // 256 j-tiles

// ---------------- precomputed 3-way bf16 split of W ----------------
__device__ uint4 g_h4[Nn * Dd / 8];   // 4 MB each, [row][k] bf16, 8 per uint4
__device__ uint4 g_m4[Nn * Dd / 8];
__device__ uint4 g_l4[Nn * Dd / 8];

__global__ void split_kernel(const float* __restrict__ W)
{
    int g = blockIdx.x * blockDim.x + threadIdx.x;
    int i = g * 8;
    float4 x0 = *(const float4*)(W + i);
    float4 x1 = *(const float4*)(W + i + 4);
    float xv[8] = {x0.x, x0.y, x0.z, x0.w, x1.x, x1.y, x1.z, x1.w};
    union { __nv_bfloat16 b[8]; uint4 v; } h, m, l;
#pragma unroll
    for (int q = 0; q < 8; q++) {
        float x = xv[q];
        __nv_bfloat16 hb = __float2bfloat16(x);
        float r1 = x - __bfloat162float(hb);
        __nv_bfloat16 mb = __float2bfloat16(r1);
        float r2 = r1 - __bfloat162float(mb);
        h.b[q] = hb; m.b[q] = mb; l.b[q] = __float2bfloat16(r2);
    }
    g_h4[g] = h.v; g_m4[g] = m.v; g_l4[g] = l.v;
}

// ---------------- helpers ----------------
__device__ __forceinline__ uint32_t smem_u32(const void* p)
{
    uint32_t a;
    asm("{ .reg .u64 t; cvta.to.shared.u64 t, %1; cvt.u32.u64 %0, t; }" : "=r"(a) : "l"(p));
    return a;
}
__device__ __forceinline__ void ldsm4(uint32_t* r, uint32_t addr)
{
    asm volatile("ldmatrix.sync.aligned.m8n8.x4.shared.b16 {%0,%1,%2,%3}, [%4];"
                 : "=r"(r[0]), "=r"(r[1]), "=r"(r[2]), "=r"(r[3]) : "r"(addr));
}
__device__ __forceinline__ void mma16816(float* c, const uint32_t* a,
                                         uint32_t b0, uint32_t b1)
{
    asm volatile(
        "mma.sync.aligned.m16n8k16.row.col.f32.bf16.bf16.f32 "
        "{%0,%1,%2,%3}, {%4,%5,%6,%7}, {%8,%9}, {%0,%1,%2,%3};"
        : "+f"(c[0]), "+f"(c[1]), "+f"(c[2]), "+f"(c[3])
        : "r"(a[0]), "r"(a[1]), "r"(a[2]), "r"(a[3]), "r"(b0), "r"(b1));
}
__device__ __forceinline__ void cp16(uint32_t dst, const void* src)
{
    asm volatile("cp.async.cg.shared.global [%0], [%1], 16;" :: "r"(dst), "l"(src));
}
#define CP_COMMIT() asm volatile("cp.async.commit_group;" ::: "memory")
#define CP_WAIT1()  asm volatile("cp.async.wait_group 1;" ::: "memory")

// ---------------- SMEM layout (bytes) ----------------
#define SM_A   0u          // 3 mats x 32KB, rows 256B, swizzle u^(row&7)
#define SM_B   98304u      // 2 stages x 3 mats x 8KB ([64 n][64 k], rows 128B)
#define SM_C   147456u     // 128 x 65 f32
#define SM_TV  180736u     // 128*32 f32
#define SM_TI  197120u     // 128*32 i32
#define SM_TOTAL 213504u

__global__ __launch_bounds__(256, 1)
void gsl_hmma_kernel(float* __restrict__ out)
{
    extern __shared__ char sm[];
    const uint32_t smb = smem_u32(sm);
    const int tid = threadIdx.x;
    const int wid = tid >> 5;
    const int lane = tid & 31;
    const int rb = blockIdx.x * BM;

    float* Cs = (float*)(sm + SM_C);
    float* TV = (float*)(sm + SM_TV);
    int*   TI = (int*)(sm + SM_TI);

    // ---- B stage loader: [64 n][64 k] per mat, rows 128B, swizzle u^(n&7) ----
    auto loadB = [&](int nb, int kh, int st) {
#pragma unroll
        for (int s = 0; s < 6; s++) {
            int idx = tid + 256 * s;        // 0..1535
            int mat = idx >> 9;
            int r2  = idx & 511;
            int n   = r2 >> 3;
            int u   = r2 & 7;
            const uint4* base = (mat == 0) ? g_h4 : (mat == 1) ? g_m4 : g_l4;
            uint32_t dst = smb + SM_B + (uint32_t)st * 24576u + (uint32_t)mat * 8192u
                         + (uint32_t)n * 128u + (uint32_t)((u ^ (n & 7)) << 4);
            cp16(dst, base + (nb + n) * 16 + kh * 8 + u);
        }
        CP_COMMIT();
    };

    // prefetch tile 0, both k-halves (slots 0,1)
    loadB(0, 0, 0);
    loadB(0, 1, 1);

    for (int i = tid; i < 128 * 32; i += 256) { TV[i] = -FLT_MAX; TI[i] = 0; }

    // ---- resident A tile: 3 mats, swizzled ----
#pragma unroll
    for (int s = 0; s < 24; s++) {
        int idx = tid + 256 * s;            // 0..6143
        int mat = idx >> 11;
        int r2  = idx & 2047;
        int row = r2 >> 4;
        int u   = r2 & 15;
        const uint4* base = (mat == 0) ? g_h4 : (mat == 1) ? g_m4 : g_l4;
        uint4 v = base[(rb + row) * 16 + u];
        uint32_t off = SM_A + (uint32_t)mat * 32768u + (uint32_t)row * 256u
                     + (uint32_t)((u ^ (row & 7)) << 4);
        *(uint4*)(sm + off) = v;
    }

    // ---- per-lane ldmatrix constants ----
    const int l7 = lane & 7;
    const int b4 = (lane >> 4) & 1;
    const int lrow = l7 + 8 * ((lane >> 3) & 1);   // 0..15
    const int wy = wid >> 2, wx = wid & 3;         // 2x4 warp grid, 64x16 each

    uint32_t abase[4];
#pragma unroll
    for (int i = 0; i < 4; i++)
        abase[i] = smb + SM_A + (uint32_t)(64 * wy + 16 * i + lrow) * 256u;
    const uint32_t bofs = (uint32_t)(16 * wx + lrow) * 128u;

    __syncthreads();   // A tile + init visible

    float vmin = -FLT_MAX;
    float* tvr = TV + tid * 32;
    int*   tir = TI + tid * 32;

    // double-buffered fragments (software pipeline, distance 1 within each k-half)
    uint32_t ah[2][4][4], am[2][4][4], al[2][4][4], bh[2][4], bm[2][4], bl[2][4];

    for (int j = 0; j < NT; j++) {
        const int jb = j * BN;
        float c[4][2][4];
#pragma unroll
        for (int i = 0; i < 4; i++)
#pragma unroll
            for (int nh = 0; nh < 2; nh++)
#pragma unroll
                for (int q = 0; q < 4; q++) c[i][nh][q] = 0.0f;

#pragma unroll
        for (int g = 0; g < 2; g++) {
            const int gg = 2 * j + g;
            CP_WAIT1();
            __syncthreads();
            const uint32_t bb = smb + SM_B + (uint32_t)(gg & 1) * 24576u;

            // fragment loader for k-step kk2 (0..3 within this half) into buffer fb
            auto loadF = [&](int kk2, int fb) {
                const int kk = g * 4 + kk2;
                const uint32_t ca = (uint32_t)(((2 * kk + b4) ^ l7) << 4);
                const uint32_t cb = (uint32_t)(((2 * kk2 + b4) ^ l7) << 4);
#pragma unroll
                for (int i = 0; i < 4; i++) {
                    ldsm4(ah[fb][i], abase[i] + ca);
                    ldsm4(am[fb][i], abase[i] + 32768u + ca);
                    ldsm4(al[fb][i], abase[i] + 65536u + ca);
                }
                ldsm4(bh[fb], bb + bofs + cb);
                ldsm4(bm[fb], bb + 8192u + bofs + cb);
                ldsm4(bl[fb], bb + 16384u + bofs + cb);
            };

            loadF(0, 0);   // prologue: first k-step of this half
#pragma unroll
            for (int kk2 = 0; kk2 < 4; kk2++) {
                const int cur = kk2 & 1;
                if (kk2 < 3) loadF(kk2 + 1, cur ^ 1);   // prefetch next step's frags
#pragma unroll
                for (int i = 0; i < 4; i++) {
                    mma16816(c[i][0], ah[cur][i], bh[cur][0], bh[cur][2]);   // h·h
                    mma16816(c[i][1], ah[cur][i], bh[cur][1], bh[cur][3]);
                    mma16816(c[i][0], ah[cur][i], bm[cur][0], bm[cur][2]);   // h·m
                    mma16816(c[i][1], ah[cur][i], bm[cur][1], bm[cur][3]);
                    mma16816(c[i][0], am[cur][i], bh[cur][0], bh[cur][2]);   // m·h
                    mma16816(c[i][1], am[cur][i], bh[cur][1], bh[cur][3]);
                    mma16816(c[i][0], ah[cur][i], bl[cur][0], bl[cur][2]);   // h·l
                    mma16816(c[i][1], ah[cur][i], bl[cur][1], bl[cur][3]);
                    mma16816(c[i][0], al[cur][i], bh[cur][0], bh[cur][2]);   // l·h
                    mma16816(c[i][1], al[cur][i], bh[cur][1], bh[cur][3]);
                    mma16816(c[i][0], am[cur][i], bm[cur][0], bm[cur][2]);   // m·m
                    mma16816(c[i][1], am[cur][i], bm[cur][1], bm[cur][3]);
                }
            }
            __syncthreads();                  // all warps done reading this slot
            int nxt = gg + 2;
            if (nxt < 2 * NT) loadB((nxt >> 1) * BN, nxt & 1, nxt & 1);
            else CP_COMMIT();
        }

        // ---- stage C to smem ----
#pragma unroll
        for (int i = 0; i < 4; i++)
#pragma unroll
            for (int nh = 0; nh < 2; nh++) {
                int row = 64 * wy + 16 * i + (lane >> 2);
                int col = 16 * wx + 8 * nh + 2 * (lane & 3);
                Cs[row * 65 + col]           = c[i][nh][0];
                Cs[row * 65 + col + 1]       = c[i][nh][1];
                Cs[(row + 8) * 65 + col]     = c[i][nh][2];
                Cs[(row + 8) * 65 + col + 1] = c[i][nh][3];
            }
        __syncthreads();

        // ---- fused top-32 scan ----
        if (tid < 128) {
            const float* crow = Cs + tid * 65;   // banks (tid + c) % 32: conflict-free
#pragma unroll 4
            for (int cc = 0; cc < BN; cc++) {
                float v = crow[cc];
                if (v > vmin) {
                    int ci = jb + cc;
                    int p = 0;
                    while (p < 31 && tvr[p + 1] < v) {
                        tvr[p] = tvr[p + 1];
                        tir[p] = tir[p + 1];
                        p++;
                    }
                    tvr[p] = v;
                    tir[p] = ci;
                    vmin = tvr[0];
                }
            }
        }
        __syncthreads();
    }

    // ---- sort by column index ascending + emit ----
    if (tid < 128) {
        for (int s = 1; s < KK; s++) {
            int   ii = tir[s];
            float vv = tvr[s];
            int p = s - 1;
            while (p >= 0 && tir[p] > ii) {
                tir[p + 1] = tir[p];
                tvr[p + 1] = tvr[p];
                p--;
            }
            tir[p + 1] = ii;
            tvr[p + 1] = vv;
        }
        const long long NK = (long long)Nn * KK;
        const long long grow = rb + tid;
        float* o = out + grow * KK;
        float growf = (float)grow;
#pragma unroll
        for (int i = 0; i < KK; i++) {
            o[i]          = growf;
            o[NK + i]     = (float)tir[i];
            o[2 * NK + i] = tvr[i];
        }
    }
}

extern "C" void kernel_launch(void* const* d_in, const int* in_sizes, int n_in,
                              void* d_out, int out_size)
{
    const float* W = (const float*)d_in[n_in > 1 ? 1 : 0];
    for (int i = 0; i < n_in; i++)
        if (in_sizes[i] == Nn * Dd) { W = (const float*)d_in[i]; break; }

    split_kernel<<<Nn * Dd / 8 / 256, 256>>>(W);

    cudaFuncSetAttribute(gsl_hmma_kernel,
                         cudaFuncAttributeMaxDynamicSharedMemorySize, SM_TOTAL);
    gsl_hmma_kernel<<<Nn / BM, 256, SM_TOTAL>>>((float*)d_out);
    (void)out_size;
}

// round 12
// speedup vs baseline: 1.0523x; 1.0523x over previous
#include <cuda_runtime.h>
#include <cuda_bf16.h>
#include <cstdint>
#include <float.h>

#define Nn    16384
#define Dd    128
#define KK    32
#define BM    64         // rows per CTA
#define BN    64         // cols per j-tile
#define NT    (Nn / BN)  // 256 j-tiles

// ---------------- precomputed 3-way bf16 split of W ----------------
__device__ uint4 g_h4[Nn * Dd / 8];   // 4 MB each, [row][k] bf16, 8 per uint4
__device__ uint4 g_m4[Nn * Dd / 8];
__device__ uint4 g_l4[Nn * Dd / 8];

__global__ void split_kernel(const float* __restrict__ W)
{
    int g = blockIdx.x * blockDim.x + threadIdx.x;
    int i = g * 8;
    float4 x0 = *(const float4*)(W + i);
    float4 x1 = *(const float4*)(W + i + 4);
    float xv[8] = {x0.x, x0.y, x0.z, x0.w, x1.x, x1.y, x1.z, x1.w};
    union { __nv_bfloat16 b[8]; uint4 v; } h, m, l;
#pragma unroll
    for (int q = 0; q < 8; q++) {
        float x = xv[q];
        __nv_bfloat16 hb = __float2bfloat16(x);
        float r1 = x - __bfloat162float(hb);
        __nv_bfloat16 mb = __float2bfloat16(r1);
        float r2 = r1 - __bfloat162float(mb);
        h.b[q] = hb; m.b[q] = mb; l.b[q] = __float2bfloat16(r2);
    }
    g_h4[g] = h.v; g_m4[g] = m.v; g_l4[g] = l.v;
}

// ---------------- helpers ----------------
__device__ __forceinline__ uint32_t smem_u32(const void* p)
{
    uint32_t a;
    asm("{ .reg .u64 t; cvta.to.shared.u64 t, %1; cvt.u32.u64 %0, t; }" : "=r"(a) : "l"(p));
    return a;
}
__device__ __forceinline__ void ldsm4(uint32_t* r, uint32_t addr)
{
    asm volatile("ldmatrix.sync.aligned.m8n8.x4.shared.b16 {%0,%1,%2,%3}, [%4];"
                 : "=r"(r[0]), "=r"(r[1]), "=r"(r[2]), "=r"(r[3]) : "r"(addr));
}
__device__ __forceinline__ void mma16816(float* c, const uint32_t* a,
                                         uint32_t b0, uint32_t b1)
{
    asm volatile(
        "mma.sync.aligned.m16n8k16.row.col.f32.bf16.bf16.f32 "
        "{%0,%1,%2,%3}, {%4,%5,%6,%7}, {%8,%9}, {%0,%1,%2,%3};"
        : "+f"(c[0]), "+f"(c[1]), "+f"(c[2]), "+f"(c[3])
        : "r"(a[0]), "r"(a[1]), "r"(a[2]), "r"(a[3]), "r"(b0), "r"(b1));
}
__device__ __forceinline__ void cp16(uint32_t dst, const void* src)
{
    asm volatile("cp.async.cg.shared.global [%0], [%1], 16;" :: "r"(dst), "l"(src));
}
#define CP_COMMIT() asm volatile("cp.async.commit_group;" ::: "memory")
#define CP_WAIT1()  asm volatile("cp.async.wait_group 1;" ::: "memory")

// ---------------- SMEM layout (bytes) ----------------
#define SM_A   0u          // 3 mats x 16KB (64 rows x 256B), swizzle u^(row&7)
#define SM_B   49152u      // 2 stages x 3 mats x 4KB ([64 n][32 k] rows 64B, swz u^(n&3))
#define SM_C   73728u      // 64 x 65 f32
#define SM_TV  90368u      // 64*32 f32
#define SM_TI  98560u      // 64*32 i32
#define SM_TOTAL 106752u   // 104.25 KB -> 2 CTAs/SM

__global__ __launch_bounds__(256, 2)
void gsl_hmma_kernel(float* __restrict__ out)
{
    extern __shared__ char sm[];
    const uint32_t smb = smem_u32(sm);
    const int tid = threadIdx.x;
    const int wid = tid >> 5;
    const int lane = tid & 31;
    const int rb = blockIdx.x * BM;

    float* Cs = (float*)(sm + SM_C);
    float* TV = (float*)(sm + SM_TV);
    int*   TI = (int*)(sm + SM_TI);

    // ---- B k-quarter loader: [64 n][32 k] per mat, rows 64B, swizzle u^(n&3) ----
    auto loadB = [&](int nb, int q, int st) {
#pragma unroll
        for (int s = 0; s < 3; s++) {
            int idx = tid + 256 * s;        // 0..767
            int mat = idx >> 8;
            int r2  = idx & 255;
            int n   = r2 >> 2;
            int u   = r2 & 3;
            const uint4* base = (mat == 0) ? g_h4 : (mat == 1) ? g_m4 : g_l4;
            uint32_t dst = smb + SM_B + (uint32_t)st * 12288u + (uint32_t)mat * 4096u
                         + (uint32_t)n * 64u + (uint32_t)((u ^ (n & 3)) << 4);
            cp16(dst, base + (nb + n) * 16 + q * 4 + u);
        }
        CP_COMMIT();
    };

    // prefetch tile 0, quarters 0,1 into slots 0,1
    loadB(0, 0, 0);
    loadB(0, 1, 1);

    for (int i = tid; i < 64 * 32; i += 256) { TV[i] = -FLT_MAX; TI[i] = 0; }

    // ---- resident A tile: 3 mats x 64 rows, swizzled ----
#pragma unroll
    for (int s = 0; s < 12; s++) {
        int idx = tid + 256 * s;            // 0..3071
        int mat = idx >> 10;
        int r2  = idx & 1023;
        int row = r2 >> 4;
        int u   = r2 & 15;
        const uint4* base = (mat == 0) ? g_h4 : (mat == 1) ? g_m4 : g_l4;
        uint4 v = base[(rb + row) * 16 + u];
        uint32_t off = SM_A + (uint32_t)mat * 16384u + (uint32_t)row * 256u
                     + (uint32_t)((u ^ (row & 7)) << 4);
        *(uint4*)(sm + off) = v;
    }

    // ---- per-lane ldmatrix constants ----
    const int l7 = lane & 7;
    const int b4 = (lane >> 4) & 1;
    const int lrow = l7 + 8 * ((lane >> 3) & 1);   // 0..15
    const int wy = wid >> 2, wx = wid & 3;         // 2x4 warp grid, 32x16 each

    uint32_t abase[2];
#pragma unroll
    for (int i = 0; i < 2; i++)
        abase[i] = smb + SM_A + (uint32_t)(32 * wy + 16 * i + lrow) * 256u;
    const int brow = 16 * wx + lrow;               // B n-row for this lane
    const uint32_t bbase = (uint32_t)brow * 64u;
    const int bsw = brow & 3;

    __syncthreads();   // A tile + init visible

    float vmin = -FLT_MAX;
    float* tvr = TV + tid * 32;
    int*   tir = TI + tid * 32;

    for (int j = 0; j < NT; j++) {
        const int jb = j * BN;
        float c[2][2][4];
#pragma unroll
        for (int i = 0; i < 2; i++)
#pragma unroll
            for (int nh = 0; nh < 2; nh++)
#pragma unroll
                for (int q = 0; q < 4; q++) c[i][nh][q] = 0.0f;

#pragma unroll
        for (int q = 0; q < 4; q++) {        // 4 k-quarters per tile
            const int qg = 4 * j + q;
            CP_WAIT1();
            __syncthreads();
            const uint32_t bb = smb + SM_B + (uint32_t)(qg & 1) * 12288u;
#pragma unroll
            for (int kk2 = 0; kk2 < 2; kk2++) {
                const int kk = q * 2 + kk2;
                const uint32_t ca = (uint32_t)(((2 * kk + b4) ^ l7) << 4);
                const uint32_t cb = (uint32_t)(((2 * kk2 + b4) ^ bsw) << 4);
                uint32_t ah[2][4], am[2][4], al[2][4], bh[4], bm[4], bl[4];
#pragma unroll
                for (int i = 0; i < 2; i++) {
                    ldsm4(ah[i], abase[i] + ca);
                    ldsm4(am[i], abase[i] + 16384u + ca);
                    ldsm4(al[i], abase[i] + 32768u + ca);
                }
                ldsm4(bh, bb + bbase + cb);
                ldsm4(bm, bb + 4096u + bbase + cb);
                ldsm4(bl, bb + 8192u + bbase + cb);
#pragma unroll
                for (int i = 0; i < 2; i++) {
                    mma16816(c[i][0], ah[i], bh[0], bh[2]);   // h·h
                    mma16816(c[i][1], ah[i], bh[1], bh[3]);
                    mma16816(c[i][0], ah[i], bm[0], bm[2]);   // h·m
                    mma16816(c[i][1], ah[i], bm[1], bm[3]);
                    mma16816(c[i][0], am[i], bh[0], bh[2]);   // m·h
                    mma16816(c[i][1], am[i], bh[1], bh[3]);
                    mma16816(c[i][0], ah[i], bl[0], bl[2]);   // h·l
                    mma16816(c[i][1], ah[i], bl[1], bl[3]);
                    mma16816(c[i][0], al[i], bh[0], bh[2]);   // l·h
                    mma16816(c[i][1], al[i], bh[1], bh[3]);
                    mma16816(c[i][0], am[i], bm[0], bm[2]);   // m·m
                    mma16816(c[i][1], am[i], bm[1], bm[3]);
                }
            }
            __syncthreads();                  // all warps done reading this slot
            int nq = qg + 2;
            if (nq < 4 * NT) loadB((nq >> 2) * BN, nq & 3, nq & 1);
            else CP_COMMIT();
        }

        // ---- stage C to smem ----
#pragma unroll
        for (int i = 0; i < 2; i++)
#pragma unroll
            for (int nh = 0; nh < 2; nh++) {
                int row = 32 * wy + 16 * i + (lane >> 2);
                int col = 16 * wx + 8 * nh + 2 * (lane & 3);
                Cs[row * 65 + col]           = c[i][nh][0];
                Cs[row * 65 + col + 1]       = c[i][nh][1];
                Cs[(row + 8) * 65 + col]     = c[i][nh][2];
                Cs[(row + 8) * 65 + col + 1] = c[i][nh][3];
            }
        __syncthreads();

        // ---- fused top-32 scan (threads 0..63, one row each) ----
        if (tid < 64) {
            const float* crow = Cs + tid * 65;   // banks (tid + c) % 32: conflict-free
#pragma unroll 4
            for (int cc = 0; cc < BN; cc++) {
                float v = crow[cc];
                if (v > vmin) {
                    int ci = jb + cc;
                    int p = 0;
                    while (p < 31 && tvr[p + 1] < v) {
                        tvr[p] = tvr[p + 1];
                        tir[p] = tir[p + 1];
                        p++;
                    }
                    tvr[p] = v;
                    tir[p] = ci;
                    vmin = tvr[0];
                }
            }
        }
        __syncthreads();
    }

    // ---- sort by column index ascending + emit ----
    if (tid < 64) {
        for (int s = 1; s < KK; s++) {
            int   ii = tir[s];
            float vv = tvr[s];
            int p = s - 1;
            while (p >= 0 && tir[p] > ii) {
                tir[p + 1] = tir[p];
                tvr[p + 1] = tvr[p];
                p--;
            }
            tir[p + 1] = ii;
            tvr[p + 1] = vv;
        }
        const long long NK = (long long)Nn * KK;
        const long long grow = rb + tid;
        float* o = out + grow * KK;
        float growf = (float)grow;
#pragma unroll
        for (int i = 0; i < KK; i++) {
            o[i]          = growf;
            o[NK + i]     = (float)tir[i];
            o[2 * NK + i] = tvr[i];
        }
    }
}

extern "C" void kernel_launch(void* const* d_in, const int* in_sizes, int n_in,
                              void* d_out, int out_size)
{
    const float* W = (const float*)d_in[n_in > 1 ? 1 : 0];
    for (int i = 0; i < n_in; i++)
        if (in_sizes[i] == Nn * Dd) { W = (const float*)d_in[i]; break; }

    split_kernel<<<Nn * Dd / 8 / 256, 256>>>(W);

    cudaFuncSetAttribute(gsl_hmma_kernel,
                         cudaFuncAttributeMaxDynamicSharedMemorySize, SM_TOTAL);
    gsl_hmma_kernel<<<Nn / BM, 256, SM_TOTAL>>>((float*)d_out);
    (void)out_size;
}

// round 13
// speedup vs baseline: 1.3031x; 1.2383x over previous
#include <cuda_runtime.h>
#include <cuda_bf16.h>
#include <cstdint>
#include <float.h>

#define Nn    16384
#define Dd    128
#define KK    32
#define BM    64         // rows per CTA
#define BN    64         // cols per j-tile
#define NT    (Nn / BN)  // 256 j-tiles

// ---------------- precomputed 3-way bf16 split of W ----------------
__device__ uint4 g_h4[Nn * Dd / 8];   // 4 MB each, [row][k] bf16, 8 per uint4
__device__ uint4 g_m4[Nn * Dd / 8];
__device__ uint4 g_l4[Nn * Dd / 8];

__global__ void split_kernel(const float* __restrict__ W)
{
    int g = blockIdx.x * blockDim.x + threadIdx.x;
    int i = g * 8;
    float4 x0 = *(const float4*)(W + i);
    float4 x1 = *(const float4*)(W + i + 4);
    float xv[8] = {x0.x, x0.y, x0.z, x0.w, x1.x, x1.y, x1.z, x1.w};
    union { __nv_bfloat16 b[8]; uint4 v; } h, m, l;
#pragma unroll
    for (int q = 0; q < 8; q++) {
        float x = xv[q];
        __nv_bfloat16 hb = __float2bfloat16(x);
        float r1 = x - __bfloat162float(hb);
        __nv_bfloat16 mb = __float2bfloat16(r1);
        float r2 = r1 - __bfloat162float(mb);
        h.b[q] = hb; m.b[q] = mb; l.b[q] = __float2bfloat16(r2);
    }
    g_h4[g] = h.v; g_m4[g] = m.v; g_l4[g] = l.v;
}

// ---------------- helpers ----------------
__device__ __forceinline__ uint32_t smem_u32(const void* p)
{
    uint32_t a;
    asm("{ .reg .u64 t; cvta.to.shared.u64 t, %1; cvt.u32.u64 %0, t; }" : "=r"(a) : "l"(p));
    return a;
}
__device__ __forceinline__ void ldsm4(uint32_t* r, uint32_t addr)
{
    asm volatile("ldmatrix.sync.aligned.m8n8.x4.shared.b16 {%0,%1,%2,%3}, [%4];"
                 : "=r"(r[0]), "=r"(r[1]), "=r"(r[2]), "=r"(r[3]) : "r"(addr));
}
__device__ __forceinline__ void mma16816(float* c, const uint32_t* a,
                                         uint32_t b0, uint32_t b1)
{
    asm volatile(
        "mma.sync.aligned.m16n8k16.row.col.f32.bf16.bf16.f32 "
        "{%0,%1,%2,%3}, {%4,%5,%6,%7}, {%8,%9}, {%0,%1,%2,%3};"
        : "+f"(c[0]), "+f"(c[1]), "+f"(c[2]), "+f"(c[3])
        : "r"(a[0]), "r"(a[1]), "r"(a[2]), "r"(a[3]), "r"(b0), "r"(b1));
}
__device__ __forceinline__ void cp16(uint32_t dst, const void* src)
{
    asm volatile("cp.async.cg.shared.global [%0], [%1], 16;" :: "r"(dst), "l"(src));
}
#define CP_COMMIT() asm volatile("cp.async.commit_group;" ::: "memory")
#define CP_WAIT1()  asm volatile("cp.async.wait_group 1;" ::: "memory")

// ---------------- SMEM layout (bytes) ----------------
#define SM_A   0u          // 3 mats x 16KB (64 rows x 256B), swizzle u^(row&7)
#define SM_B   49152u      // 2 stages x 3 mats x 4KB ([64 n][32 k] rows 64B, swz u^(n&3))
#define SM_C   73728u      // 64 x 65 f32
#define SM_TV  90368u      // 64*32 f32
#define SM_TI  98560u      // 64*32 i32
#define SM_TOTAL 106752u   // 104.25 KB -> 2 CTAs/SM

__global__ __launch_bounds__(256, 2)
void gsl_hmma_kernel(float* __restrict__ out)
{
    extern __shared__ char sm[];
    const uint32_t smb = smem_u32(sm);
    const int tid = threadIdx.x;
    const int wid = tid >> 5;
    const int lane = tid & 31;
    const int rb = blockIdx.x * BM;

    float* Cs = (float*)(sm + SM_C);
    float* TV = (float*)(sm + SM_TV);
    int*   TI = (int*)(sm + SM_TI);

    // ---- B k-quarter loader: [64 n][32 k] per mat, rows 64B, swizzle u^(n&3) ----
    auto loadB = [&](int nb, int q, int st) {
#pragma unroll
        for (int s = 0; s < 3; s++) {
            int idx = tid + 256 * s;        // 0..767
            int mat = idx >> 8;
            int r2  = idx & 255;
            int n   = r2 >> 2;
            int u   = r2 & 3;
            const uint4* base = (mat == 0) ? g_h4 : (mat == 1) ? g_m4 : g_l4;
            uint32_t dst = smb + SM_B + (uint32_t)st * 12288u + (uint32_t)mat * 4096u
                         + (uint32_t)n * 64u + (uint32_t)((u ^ (n & 3)) << 4);
            cp16(dst, base + (nb + n) * 16 + q * 4 + u);
        }
        CP_COMMIT();
    };

    // prefetch tile 0, quarters 0,1 into slots 0,1
    loadB(0, 0, 0);
    loadB(0, 1, 1);

    for (int i = tid; i < 64 * 32; i += 256) TI[i] = 0;

    // ---- resident A tile: 3 mats x 64 rows, swizzled ----
#pragma unroll
    for (int s = 0; s < 12; s++) {
        int idx = tid + 256 * s;            // 0..3071
        int mat = idx >> 10;
        int r2  = idx & 1023;
        int row = r2 >> 4;
        int u   = r2 & 15;
        const uint4* base = (mat == 0) ? g_h4 : (mat == 1) ? g_m4 : g_l4;
        uint4 v = base[(rb + row) * 16 + u];
        uint32_t off = SM_A + (uint32_t)mat * 16384u + (uint32_t)row * 256u
                     + (uint32_t)((u ^ (row & 7)) << 4);
        *(uint4*)(sm + off) = v;
    }

    // ---- per-lane ldmatrix constants ----
    const int l7 = lane & 7;
    const int b4 = (lane >> 4) & 1;
    const int lrow = l7 + 8 * ((lane >> 3) & 1);   // 0..15
    const int wy = wid >> 2, wx = wid & 3;         // 2x4 warp grid, 32x16 each

    uint32_t abase[2];
#pragma unroll
    for (int i = 0; i < 2; i++)
        abase[i] = smb + SM_A + (uint32_t)(32 * wy + 16 * i + lrow) * 256u;
    const int brow = 16 * wx + lrow;               // B n-row for this lane
    const uint32_t bbase = (uint32_t)brow * 64u;
    const int bsw = brow & 3;

    // ---- register-resident top-32 (rows spread over all 8 warps, lanes 0..7) ----
    const int myrow = wid * 8 + (lane & 7);        // valid when lane < 8
    float tv[KK];
#pragma unroll
    for (int s = 0; s < KK; s++) tv[s] = -FLT_MAX;
    float vmin = -FLT_MAX;
    int* tirow = TI + myrow * KK;

    __syncthreads();   // A tile + TI init visible

    for (int j = 0; j < NT; j++) {
        const int jb = j * BN;
        float c[2][2][4];
#pragma unroll
        for (int i = 0; i < 2; i++)
#pragma unroll
            for (int nh = 0; nh < 2; nh++)
#pragma unroll
                for (int q = 0; q < 4; q++) c[i][nh][q] = 0.0f;

#pragma unroll
        for (int q = 0; q < 4; q++) {        // 4 k-quarters per tile
            const int qg = 4 * j + q;
            CP_WAIT1();
            __syncthreads();
            const uint32_t bb = smb + SM_B + (uint32_t)(qg & 1) * 12288u;
#pragma unroll
            for (int kk2 = 0; kk2 < 2; kk2++) {
                const int kk = q * 2 + kk2;
                const uint32_t ca = (uint32_t)(((2 * kk + b4) ^ l7) << 4);
                const uint32_t cb = (uint32_t)(((2 * kk2 + b4) ^ bsw) << 4);
                uint32_t ah[2][4], am[2][4], al[2][4], bh[4], bm[4], bl[4];
#pragma unroll
                for (int i = 0; i < 2; i++) {
                    ldsm4(ah[i], abase[i] + ca);
                    ldsm4(am[i], abase[i] + 16384u + ca);
                    ldsm4(al[i], abase[i] + 32768u + ca);
                }
                ldsm4(bh, bb + bbase + cb);
                ldsm4(bm, bb + 4096u + bbase + cb);
                ldsm4(bl, bb + 8192u + bbase + cb);
#pragma unroll
                for (int i = 0; i < 2; i++) {
                    mma16816(c[i][0], ah[i], bh[0], bh[2]);   // h·h
                    mma16816(c[i][1], ah[i], bh[1], bh[3]);
                    mma16816(c[i][0], ah[i], bm[0], bm[2]);   // h·m
                    mma16816(c[i][1], ah[i], bm[1], bm[3]);
                    mma16816(c[i][0], am[i], bh[0], bh[2]);   // m·h
                    mma16816(c[i][1], am[i], bh[1], bh[3]);
                    mma16816(c[i][0], ah[i], bl[0], bl[2]);   // h·l
                    mma16816(c[i][1], ah[i], bl[1], bl[3]);
                    mma16816(c[i][0], al[i], bh[0], bh[2]);   // l·h
                    mma16816(c[i][1], al[i], bh[1], bh[3]);
                    mma16816(c[i][0], am[i], bm[0], bm[2]);   // m·m
                    mma16816(c[i][1], am[i], bm[1], bm[3]);
                }
            }
            __syncthreads();                  // all warps done reading this slot
            int nq = qg + 2;
            if (nq < 4 * NT) loadB((nq >> 2) * BN, nq & 3, nq & 1);
            else CP_COMMIT();
        }

        // ---- stage C to smem ----
#pragma unroll
        for (int i = 0; i < 2; i++)
#pragma unroll
            for (int nh = 0; nh < 2; nh++) {
                int row = 32 * wy + 16 * i + (lane >> 2);
                int col = 16 * wx + 8 * nh + 2 * (lane & 3);
                Cs[row * 65 + col]           = c[i][nh][0];
                Cs[row * 65 + col + 1]       = c[i][nh][1];
                Cs[(row + 8) * 65 + col]     = c[i][nh][2];
                Cs[(row + 8) * 65 + col + 1] = c[i][nh][3];
            }
        __syncthreads();

        // ---- fused top-32 scan: 8 rows per warp (lanes 0..7), register list ----
        if (lane < 8) {
            const float* crow = Cs + myrow * 65;   // banks (myrow + c) % 32: conflict-free
            for (int cc = 0; cc < BN; cc++) {
                float v = crow[cc];
                if (v > vmin) {
                    // argmin over register array (fixed-length, branchless inside)
                    float mn = tv[0]; int am = 0;
#pragma unroll
                    for (int s = 1; s < KK; s++)
                        if (tv[s] < mn) { mn = tv[s]; am = s; }
                    // replace min slot
#pragma unroll
                    for (int s = 0; s < KK; s++)
                        if (s == am) tv[s] = v;
                    tirow[am] = jb + cc;
                    // recompute threshold
                    float m2 = tv[0];
#pragma unroll
                    for (int s = 1; s < KK; s++) m2 = fminf(m2, tv[s]);
                    vmin = m2;
                }
            }
        }
        __syncthreads();
    }

    // ---- dump registers, sort by column index ascending, emit ----
    if (lane < 8) {
        float* tvr = TV + myrow * KK;
#pragma unroll
        for (int s = 0; s < KK; s++) tvr[s] = tv[s];
        int* tir = tirow;
        for (int s = 1; s < KK; s++) {
            int   ii = tir[s];
            float vv = tvr[s];
            int p = s - 1;
            while (p >= 0 && tir[p] > ii) {
                tir[p + 1] = tir[p];
                tvr[p + 1] = tvr[p];
                p--;
            }
            tir[p + 1] = ii;
            tvr[p + 1] = vv;
        }
        const long long NK = (long long)Nn * KK;
        const long long grow = rb + myrow;
        float* o = out + grow * KK;
        float growf = (float)grow;
#pragma unroll
        for (int i = 0; i < KK; i++) {
            o[i]          = growf;
            o[NK + i]     = (float)tir[i];
            o[2 * NK + i] = tvr[i];
        }
    }
}

extern "C" void kernel_launch(void* const* d_in, const int* in_sizes, int n_in,
                              void* d_out, int out_size)
{
    const float* W = (const float*)d_in[n_in > 1 ? 1 : 0];
    for (int i = 0; i < n_in; i++)
        if (in_sizes[i] == Nn * Dd) { W = (const float*)d_in[i]; break; }

    split_kernel<<<Nn * Dd / 8 / 256, 256>>>(W);

    cudaFuncSetAttribute(gsl_hmma_kernel,
                         cudaFuncAttributeMaxDynamicSharedMemorySize, SM_TOTAL);
    gsl_hmma_kernel<<<Nn / BM, 256, SM_TOTAL>>>((float*)d_out);
    (void)out_size;
}

// round 15
// speedup vs baseline: 1.6050x; 1.2317x over previous
#include <cuda_runtime.h>
#include <cuda_bf16.h>
#include <cstdint>
#include <float.h>

#define Nn    16384
#define Dd    128
#define KK    32
#define BM    64         // rows per CTA
#define BN    64         // cols per j-tile
#define NT    (Nn / BN)  // 256 j-tiles

// ---------------- precomputed 3-way bf16 split of W ----------------
__device__ uint4 g_h4[Nn * Dd / 8];   // 4 MB each, [row][k] bf16, 8 per uint4
__device__ uint4 g_m4[Nn * Dd / 8];
__device__ uint4 g_l4[Nn * Dd / 8];

__global__ void split_kernel(const float* __restrict__ W)
{
    int g = blockIdx.x * blockDim.x + threadIdx.x;
    int i = g * 8;
    float4 x0 = *(const float4*)(W + i);
    float4 x1 = *(const float4*)(W + i + 4);
    float xv[8] = {x0.x, x0.y, x0.z, x0.w, x1.x, x1.y, x1.z, x1.w};
    union { __nv_bfloat16 b[8]; uint4 v; } h, m, l;
#pragma unroll
    for (int q = 0; q < 8; q++) {
        float x = xv[q];
        __nv_bfloat16 hb = __float2bfloat16(x);
        float r1 = x - __bfloat162float(hb);
        __nv_bfloat16 mb = __float2bfloat16(r1);
        float r2 = r1 - __bfloat162float(mb);
        h.b[q] = hb; m.b[q] = mb; l.b[q] = __float2bfloat16(r2);
    }
    g_h4[g] = h.v; g_m4[g] = m.v; g_l4[g] = l.v;
}

// ---------------- helpers ----------------
__device__ __forceinline__ uint32_t smem_u32(const void* p)
{
    uint32_t a;
    asm("{ .reg .u64 t; cvta.to.shared.u64 t, %1; cvt.u32.u64 %0, t; }" : "=r"(a) : "l"(p));
    return a;
}
__device__ __forceinline__ void ldsm4(uint32_t* r, uint32_t addr)
{
    asm volatile("ldmatrix.sync.aligned.m8n8.x4.shared.b16 {%0,%1,%2,%3}, [%4];"
                 : "=r"(r[0]), "=r"(r[1]), "=r"(r[2]), "=r"(r[3]) : "r"(addr));
}
__device__ __forceinline__ void mma16816(float* c, const uint32_t* a,
                                         uint32_t b0, uint32_t b1)
{
    asm volatile(
        "mma.sync.aligned.m16n8k16.row.col.f32.bf16.bf16.f32 "
        "{%0,%1,%2,%3}, {%4,%5,%6,%7}, {%8,%9}, {%0,%1,%2,%3};"
        : "+f"(c[0]), "+f"(c[1]), "+f"(c[2]), "+f"(c[3])
        : "r"(a[0]), "r"(a[1]), "r"(a[2]), "r"(a[3]), "r"(b0), "r"(b1));
}
__device__ __forceinline__ void cp16(uint32_t dst, const void* src)
{
    asm volatile("cp.async.cg.shared.global [%0], [%1], 16;" :: "r"(dst), "l"(src));
}
#define CP_COMMIT() asm volatile("cp.async.commit_group;" ::: "memory")
#define CP_WAIT1()  asm volatile("cp.async.wait_group 1;" ::: "memory")

// ---------------- SMEM layout (bytes) ----------------
#define SM_A   0u          // 3 mats x 16KB (64 rows x 256B), swizzle u^(row&7)
#define SM_B   49152u      // 2 stages x 3 mats x 4KB ([64 n][32 k] rows 64B, swz u^(n&3))
#define SM_C   73728u      // 64 x 65 f32
#define SM_TV  90368u      // 64*32 f32
#define SM_TI  98560u      // 64*32 i32
#define SM_TOTAL 106752u   // 104.25 KB -> 2 CTAs/SM

__global__ __launch_bounds__(256, 2)
void gsl_hmma_kernel(float* __restrict__ out)
{
    extern __shared__ char sm[];
    const uint32_t smb = smem_u32(sm);
    const int tid = threadIdx.x;
    const int wid = tid >> 5;
    const int lane = tid & 31;
    const int rb = blockIdx.x * BM;

    float* Cs = (float*)(sm + SM_C);
    float* TV = (float*)(sm + SM_TV);
    int*   TI = (int*)(sm + SM_TI);

    // ---- B k-quarter loader: [64 n][32 k] per mat, rows 64B, swizzle u^(n&3) ----
    auto loadB = [&](int nb, int q, int st) {
#pragma unroll
        for (int s = 0; s < 3; s++) {
            int idx = tid + 256 * s;        // 0..767
            int mat = idx >> 8;
            int r2  = idx & 255;
            int n   = r2 >> 2;
            int u   = r2 & 3;
            const uint4* base = (mat == 0) ? g_h4 : (mat == 1) ? g_m4 : g_l4;
            uint32_t dst = smb + SM_B + (uint32_t)st * 12288u + (uint32_t)mat * 4096u
                         + (uint32_t)n * 64u + (uint32_t)((u ^ (n & 3)) << 4);
            cp16(dst, base + (nb + n) * 16 + q * 4 + u);
        }
        CP_COMMIT();
    };

    // prefetch tile 0, quarters 0,1 into slots 0,1
    loadB(0, 0, 0);
    loadB(0, 1, 1);

    // ---- resident A tile: 3 mats x 64 rows, swizzled ----
#pragma unroll
    for (int s = 0; s < 12; s++) {
        int idx = tid + 256 * s;            // 0..3071
        int mat = idx >> 10;
        int r2  = idx & 1023;
        int row = r2 >> 4;
        int u   = r2 & 15;
        const uint4* base = (mat == 0) ? g_h4 : (mat == 1) ? g_m4 : g_l4;
        uint4 v = base[(rb + row) * 16 + u];
        uint32_t off = SM_A + (uint32_t)mat * 16384u + (uint32_t)row * 256u
                     + (uint32_t)((u ^ (row & 7)) << 4);
        *(uint4*)(sm + off) = v;
    }

    // ---- per-lane ldmatrix constants ----
    const int l7 = lane & 7;
    const int b4 = (lane >> 4) & 1;
    const int lrow = l7 + 8 * ((lane >> 3) & 1);   // 0..15
    const int wy = wid >> 2, wx = wid & 3;         // 2x4 warp grid, 32x16 each

    uint32_t abase[2];
#pragma unroll
    for (int i = 0; i < 2; i++)
        abase[i] = smb + SM_A + (uint32_t)(32 * wy + 16 * i + lrow) * 256u;
    const int brow = 16 * wx + lrow;               // B n-row for this lane
    const uint32_t bbase = (uint32_t)brow * 64u;
    const int bsw = brow & 3;

    // ---- warp-distributed top-32: warp owns rows wid*8..wid*8+7,
    //      lane s holds slot s of each row's list ----
    float tv[8];   int ti[8];   float vmin[8];
#pragma unroll
    for (int r = 0; r < 8; r++) { tv[r] = -FLT_MAX; ti[r] = 0; vmin[r] = -FLT_MAX; }

    __syncthreads();   // A tile visible

    for (int j = 0; j < NT; j++) {
        const int jb = j * BN;
        float c[2][2][4];
#pragma unroll
        for (int i = 0; i < 2; i++)
#pragma unroll
            for (int nh = 0; nh < 2; nh++)
#pragma unroll
                for (int q = 0; q < 4; q++) c[i][nh][q] = 0.0f;

#pragma unroll
        for (int q = 0; q < 4; q++) {        // 4 k-quarters per tile
            const int qg = 4 * j + q;
            CP_WAIT1();
            __syncthreads();
            const uint32_t bb = smb + SM_B + (uint32_t)(qg & 1) * 12288u;
#pragma unroll
            for (int kk2 = 0; kk2 < 2; kk2++) {
                const int kk = q * 2 + kk2;
                const uint32_t ca = (uint32_t)(((2 * kk + b4) ^ l7) << 4);
                const uint32_t cb = (uint32_t)(((2 * kk2 + b4) ^ bsw) << 4);
                uint32_t ah[2][4], am[2][4], al[2][4], bh[4], bm[4], bl[4];
#pragma unroll
                for (int i = 0; i < 2; i++) {
                    ldsm4(ah[i], abase[i] + ca);
                    ldsm4(am[i], abase[i] + 16384u + ca);
                    ldsm4(al[i], abase[i] + 32768u + ca);
                }
                ldsm4(bh, bb + bbase + cb);
                ldsm4(bm, bb + 4096u + bbase + cb);
                ldsm4(bl, bb + 8192u + bbase + cb);
#pragma unroll
                for (int i = 0; i < 2; i++) {
                    mma16816(c[i][0], ah[i], bh[0], bh[2]);   // h·h
                    mma16816(c[i][1], ah[i], bh[1], bh[3]);
                    mma16816(c[i][0], ah[i], bm[0], bm[2]);   // h·m
                    mma16816(c[i][1], ah[i], bm[1], bm[3]);
                    mma16816(c[i][0], am[i], bh[0], bh[2]);   // m·h
                    mma16816(c[i][1], am[i], bh[1], bh[3]);
                    mma16816(c[i][0], ah[i], bl[0], bl[2]);   // h·l
                    mma16816(c[i][1], ah[i], bl[1], bl[3]);
                    mma16816(c[i][0], al[i], bh[0], bh[2]);   // l·h
                    mma16816(c[i][1], al[i], bh[1], bh[3]);
                    mma16816(c[i][0], am[i], bm[0], bm[2]);   // m·m
                    mma16816(c[i][1], am[i], bm[1], bm[3]);
                }
            }
            __syncthreads();                  // all warps done reading this slot
            int nq = qg + 2;
            if (nq < 4 * NT) loadB((nq >> 2) * BN, nq & 3, nq & 1);
            else CP_COMMIT();
        }

        // ---- stage C to smem ----
#pragma unroll
        for (int i = 0; i < 2; i++)
#pragma unroll
            for (int nh = 0; nh < 2; nh++) {
                int row = 32 * wy + 16 * i + (lane >> 2);
                int col = 16 * wx + 8 * nh + 2 * (lane & 3);
                Cs[row * 65 + col]           = c[i][nh][0];
                Cs[row * 65 + col + 1]       = c[i][nh][1];
                Cs[(row + 8) * 65 + col]     = c[i][nh][2];
                Cs[(row + 8) * 65 + col + 1] = c[i][nh][3];
            }
        __syncthreads();

        // ---- warp-cooperative top-32: 8 rows per warp, full warp per row ----
#pragma unroll 1
        for (int r = 0; r < 8; r++) {
            const int row = wid * 8 + r;
            const float* crow = Cs + row * 65;
            float v0 = crow[2 * lane];
            float v1 = crow[2 * lane + 1];
            float m = vmin[r];
            unsigned mask = __ballot_sync(0xFFFFFFFFu, (v0 > m) || (v1 > m));
            while (mask) {
                int src = __ffs(mask) - 1;
                mask &= mask - 1;
                float cv0 = __shfl_sync(0xFFFFFFFFu, v0, src);
                float cv1 = __shfl_sync(0xFFFFFFFFu, v1, src);
#pragma unroll
                for (int t = 0; t < 2; t++) {
                    float v = t ? cv1 : cv0;
                    if (v > vmin[r]) {
                        // warp argmin over distributed slots
                        float mv = tv[r]; int ml = lane;
#pragma unroll
                        for (int off = 16; off; off >>= 1) {
                            float ov = __shfl_xor_sync(0xFFFFFFFFu, mv, off);
                            int   ol = __shfl_xor_sync(0xFFFFFFFFu, ml, off);
                            if (ov < mv || (ov == mv && ol < ml)) { mv = ov; ml = ol; }
                        }
                        if (lane == ml) { tv[r] = v; ti[r] = jb + 2 * src + t; }
                        // refresh vmin
                        float nv = tv[r];
#pragma unroll
                        for (int off = 16; off; off >>= 1)
                            nv = fminf(nv, __shfl_xor_sync(0xFFFFFFFFu, nv, off));
                        vmin[r] = nv;
                    }
                }
            }
        }
        __syncthreads();
    }

    // ---- dump distributed lists to smem ----
#pragma unroll
    for (int r = 0; r < 8; r++) {
        int row = wid * 8 + r;
        TV[row * KK + lane] = tv[r];
        TI[row * KK + lane] = ti[r];
    }
    __syncthreads();

    // ---- sort by column index ascending + emit (one thread per row) ----
    if (tid < 64) {
        float* tvr = TV + tid * KK;
        int*   tir = TI + tid * KK;
        for (int s = 1; s < KK; s++) {
            int   ii = tir[s];
            float vv = tvr[s];
            int p = s - 1;
            while (p >= 0 && tir[p] > ii) {
                tir[p + 1] = tir[p];
                tvr[p + 1] = tvr[p];
                p--;
            }
            tir[p + 1] = ii;
            tvr[p + 1] = vv;
        }
        const long long NK = (long long)Nn * KK;
        const long long grow = rb + tid;
        float* o = out + grow * KK;
        float growf = (float)grow;
#pragma unroll
        for (int i = 0; i < KK; i++) {
            o[i]          = growf;
            o[NK + i]     = (float)tir[i];
            o[2 * NK + i] = tvr[i];
        }
    }
}

extern "C" void kernel_launch(void* const* d_in, const int* in_sizes, int n_in,
                              void* d_out, int out_size)
{
    const float* W = (const float*)d_in[n_in > 1 ? 1 : 0];
    for (int i = 0; i < n_in; i++)
        if (in_sizes[i] == Nn * Dd) { W = (const float*)d_in[i]; break; }

    split_kernel<<<Nn * Dd / 8 / 256, 256>>>(W);

    cudaFuncSetAttribute(gsl_hmma_kernel,
                         cudaFuncAttributeMaxDynamicSharedMemorySize, SM_TOTAL);
    gsl_hmma_kernel<<<Nn / BM, 256, SM_TOTAL>>>((float*)d_out);
    (void)out_size;
}